// round 7
// baseline (speedup 1.0000x reference)
#include <cuda_runtime.h>
#include <math.h>

#define NB 8
#define NL 4096
#define NH 8
#define NM 64
#define NCH 512

typedef unsigned long long u64x;

// ---------------- device scratch ----------------
__device__ ulonglong2 g_ts[4096];                  // (cc, ss) packed f32x2 of angle 2*pi*i/4096
__device__ float2 g_F[8 * NB * NM * NCH];          // [tq*2+tensor][b][mode-pos][ch]
__device__ float2 g_O[NB * NH * 64 * NM];          // [row][mode-pos]: (A, B) pre-scaled

// ---------------- f32x2 helpers ----------------
static __device__ __forceinline__ u64x fma2(u64x a, u64x b, u64x c) {
    u64x d; asm("fma.rn.f32x2 %0,%1,%2,%3;" : "=l"(d) : "l"(a), "l"(b), "l"(c)); return d;
}
static __device__ __forceinline__ u64x add2(u64x a, u64x b) {
    u64x d; asm("add.rn.f32x2 %0,%1,%2;" : "=l"(d) : "l"(a), "l"(b)); return d;
}
#define NEG1X2 0xBF800000BF800000ULL
#define KK2    0x3F3504F33F3504F3ULL   // (sqrt2/2, sqrt2/2)
#define NKK2   0xBF3504F3BF3504F3ULL   // negated
static __device__ __forceinline__ u64x sub2(u64x a, u64x b) { return fma2(b, NEG1X2, a); }
static __device__ __forceinline__ u64x neg2(u64x a) { return fma2(a, NEG1X2, 0ULL); }
static __device__ __forceinline__ void unpack2(u64x d, float& lo, float& hi) {
    asm("mov.b64 {%0,%1},%2;" : "=f"(lo), "=f"(hi) : "l"(d));
}

// ================= K0: trig table =================
__global__ void k0_init() {
    int i = blockIdx.x * 256 + threadIdx.x;
    if (i < 4096) {
        float s, c;
        sincospif((float)i / 2048.0f, &s, &c);
        u64x cc, ss;
        asm("mov.b64 %0,{%1,%1};" : "=l"(cc) : "f"(c));
        asm("mov.b64 %0,{%1,%1};" : "=l"(ss) : "f"(s));
        g_ts[i] = make_ulonglong2(cc, ss);
    }
}

// ================= K1: forward sparse DFT (radix-8, 8 modes/warp, 4 ch/lane) =================
// X[f] = sum_{t'} u_j(t') e^{-i 2pi f t'/4096}, j=f&7, u_j = sum_m x[t'+512m] w^{jm}, w=e^{-i pi/4}.
// accR=Re, accS accumulates -Im.
template<int CLS>
static __device__ __forceinline__ void k1_chunk8(
    const u64x* __restrict__ xsd, const ulonglong2* __restrict__ ts2,
    int lane, u64x accR[16], u64x accS[16], int idx[8], const int F[8])
{
#pragma unroll 2
    for (int tt = 0; tt < 8; tt++) {
        u64x Pr[2], Pi[2], nPi[2];
#pragma unroll
        for (int p = 0; p < 2; p++) {
            u64x a0 = xsd[((0 * 8 + tt) * 32 + lane) * 2 + p];
            u64x a1 = xsd[((1 * 8 + tt) * 32 + lane) * 2 + p];
            u64x a2 = xsd[((2 * 8 + tt) * 32 + lane) * 2 + p];
            u64x a3 = xsd[((3 * 8 + tt) * 32 + lane) * 2 + p];
            u64x a4 = xsd[((4 * 8 + tt) * 32 + lane) * 2 + p];
            u64x a5 = xsd[((5 * 8 + tt) * 32 + lane) * 2 + p];
            u64x a6 = xsd[((6 * 8 + tt) * 32 + lane) * 2 + p];
            u64x a7 = xsd[((7 * 8 + tt) * 32 + lane) * 2 + p];
            if (CLS == 0) {
                Pr[p] = add2(add2(add2(a0, a4), add2(a2, a6)), add2(add2(a1, a5), add2(a3, a7)));
            } else if (CLS == 4) {
                Pr[p] = sub2(add2(add2(a0, a4), add2(a2, a6)), add2(add2(a1, a5), add2(a3, a7)));
            } else if (CLS == 2 || CLS == 6) {
                u64x e0 = add2(a0, a4), e2 = add2(a2, a6);
                u64x e1 = add2(a1, a5), e3 = add2(a3, a7);
                Pr[p] = sub2(e0, e2);
                Pi[p] = (CLS == 2) ? sub2(e3, e1) : sub2(e1, e3);
                nPi[p] = neg2(Pi[p]);
            } else {
                u64x d04 = sub2(a0, a4), d62 = sub2(a6, a2);
                u64x s1 = sub2(a1, a5), s2 = sub2(a3, a7);
                u64x t1 = sub2(s1, s2), t2 = add2(s1, s2);
                if (CLS == 1) { Pr[p] = fma2(t1, KK2, d04);  Pi[p] = fma2(t2, NKK2, d62); }
                if (CLS == 3) { Pr[p] = fma2(t1, NKK2, d04); Pi[p] = neg2(fma2(t2, KK2, d62)); }
                if (CLS == 5) { Pr[p] = fma2(t1, NKK2, d04); Pi[p] = fma2(t2, KK2, d62); }
                if (CLS == 7) { Pr[p] = fma2(t1, KK2, d04);  Pi[p] = fma2(t2, KK2, neg2(d62)); }
                nPi[p] = neg2(Pi[p]);
            }
        }
#pragma unroll
        for (int k = 0; k < 8; k++) {
            ulonglong2 cs = ts2[idx[k]];
#pragma unroll
            for (int p = 0; p < 2; p++) {
                accR[k * 2 + p] = fma2(Pr[p], cs.x, accR[k * 2 + p]);
                accS[k * 2 + p] = fma2(Pr[p], cs.y, accS[k * 2 + p]);
                if (CLS != 0 && CLS != 4) {
                    accR[k * 2 + p] = fma2(Pi[p],  cs.y, accR[k * 2 + p]);
                    accS[k * 2 + p] = fma2(nPi[p], cs.x, accS[k * 2 + p]);
                }
            }
            idx[k] = (idx[k] + F[k]) & 4095;
        }
    }
}

// generic (mixed-class) fallback: direct per-row accumulation, no decimation
static __device__ __forceinline__ void k1_chunk_gen(
    const u64x* __restrict__ xsd, const ulonglong2* __restrict__ ts2,
    int lane, u64x accR[16], u64x accS[16], int tp0, const int F[8])
{
    for (int tt = 0; tt < 8; tt++) {
#pragma unroll
        for (int m = 0; m < 8; m++) {
            int tg = tp0 + tt + 512 * m;
#pragma unroll
            for (int p = 0; p < 2; p++) {
                u64x x = xsd[((m * 8 + tt) * 32 + lane) * 2 + p];
#pragma unroll
                for (int k = 0; k < 8; k++) {
                    int id = (F[k] * tg) & 4095;
                    ulonglong2 cs = ts2[id];
                    accR[k * 2 + p] = fma2(x, cs.x, accR[k * 2 + p]);
                    accS[k * 2 + p] = fma2(x, cs.y, accS[k * 2 + p]);
                }
            }
        }
    }
}

#define K1_SMEM (4096 * 16 + 8 * 8 * 128 * 4 + 256)
__global__ void __launch_bounds__(256, 2) k1_forward(const float* __restrict__ qp,
                                                     const float* __restrict__ kp,
                                                     const int* __restrict__ iq,
                                                     const int* __restrict__ ikv) {
    extern __shared__ char sm[];
    ulonglong2* ts2 = (ulonglong2*)sm;
    float* xs = (float*)(ts2 + 4096);            // [8 m][8 t'][128 ch]
    int* sMi = (int*)(xs + 8 * 8 * 128);         // [64]
    const u64x* xsd = (const u64x*)xs;

    const int ctile = blockIdx.x, b = blockIdx.y;
    const int tensor = blockIdx.z >> 2, tq = blockIdx.z & 3;
    const float* src = tensor ? kp : qp;
    const int* idxarr = tensor ? ikv : iq;
    const int tid = threadIdx.x, lane = tid & 31, warp = tid >> 5;

    for (int i = tid; i < 4096; i += 256) ts2[i] = g_ts[i];

    // bucket 64 modes by class (F&7); warp takes bucketed block per SMSP-balancing perm
    const int wperm_tab[8] = {0, 4, 2, 6, 1, 3, 5, 7};
    const int gw = wperm_tab[warp];
    const unsigned FULL = 0xffffffffu;
    int Flo = idxarr[lane], Fhi = idxarr[lane + 32];
    int clo = Flo & 7, chi = Fhi & 7;
    unsigned mlo[8], mhi[8];
    int off[9]; off[0] = 0;
#pragma unroll
    for (int c = 0; c < 8; c++) {
        mlo[c] = __ballot_sync(FULL, clo == c);
        mhi[c] = __ballot_sync(FULL, chi == c);
    }
#pragma unroll
    for (int c = 0; c < 8; c++) off[c + 1] = off[c] + __popc(mlo[c]) + __popc(mhi[c]);
    unsigned lm = (1u << lane) - 1u;
    int p_lo = off[clo] + __popc(mlo[clo] & lm);
    int p_hi = off[chi] + __popc(mlo[chi]) + __popc(mhi[chi] & lm);
    int F[8];
#pragma unroll
    for (int k = 0; k < 8; k++) {
        int tpos = gw * 8 + k;
        unsigned ba = __ballot_sync(FULL, p_lo == tpos);
        unsigned bb = __ballot_sync(FULL, p_hi == tpos);
        int m = ba ? (__ffs(ba) - 1) : (32 + __ffs(bb) - 1);
        if (lane == 0) sMi[tpos] = m;
        F[k] = __shfl_sync(FULL, (m < 32) ? Flo : Fhi, m & 31);
    }
    int jcls = F[0] & 7;
    bool uni = true;
#pragma unroll
    for (int k = 1; k < 8; k++) uni = uni && ((F[k] & 7) == jcls);

    u64x accR[16], accS[16]; int idx[8];
#pragma unroll
    for (int k = 0; k < 16; k++) { accR[k] = 0; accS[k] = 0; }

    const float* base = src + (size_t)b * NL * NCH + ctile * 128;

    for (int cc = 0; cc < 16; cc++) {
        const int tp0 = tq * 128 + cc * 8;
        __syncthreads();
#pragma unroll
        for (int ii = 0; ii < 8; ii++) {
            int i = ii * 256 + tid;                 // 2048 float4
            int c4 = i & 31, tt = (i >> 5) & 7, m = i >> 8;
            ((float4*)xs)[i] = *(const float4*)(base + (size_t)(tp0 + tt + 512 * m) * NCH + c4 * 4);
        }
        __syncthreads();
#pragma unroll
        for (int k = 0; k < 8; k++) idx[k] = (F[k] * tp0) & 4095;
        if (uni) {
            switch (jcls) {
                case 0: k1_chunk8<0>(xsd, ts2, lane, accR, accS, idx, F); break;
                case 1: k1_chunk8<1>(xsd, ts2, lane, accR, accS, idx, F); break;
                case 2: k1_chunk8<2>(xsd, ts2, lane, accR, accS, idx, F); break;
                case 3: k1_chunk8<3>(xsd, ts2, lane, accR, accS, idx, F); break;
                case 4: k1_chunk8<4>(xsd, ts2, lane, accR, accS, idx, F); break;
                case 5: k1_chunk8<5>(xsd, ts2, lane, accR, accS, idx, F); break;
                case 6: k1_chunk8<6>(xsd, ts2, lane, accR, accS, idx, F); break;
                default: k1_chunk8<7>(xsd, ts2, lane, accR, accS, idx, F); break;
            }
        } else {
            k1_chunk_gen(xsd, ts2, lane, accR, accS, tp0, F);
        }
    }

    const int ch = ctile * 128 + lane * 4;
    float2* dst = g_F + ((size_t)((tq * 2 + tensor) * NB + b) * NM) * NCH;
#pragma unroll
    for (int k = 0; k < 8; k++) {
        float r0, r1, r2, r3, s0, s1, s2, s3;
        unpack2(accR[k * 2 + 0], r0, r1);
        unpack2(accS[k * 2 + 0], s0, s1);
        unpack2(accR[k * 2 + 1], r2, r3);
        unpack2(accS[k * 2 + 1], s2, s3);
        int mi = sMi[gw * 8 + k];
        float2* dp = &dst[(size_t)mi * NCH + ch];
        *(float4*)(dp)     = make_float4(r0, -s0, r1, -s1);
        *(float4*)(dp + 2) = make_float4(r2, -s2, r3, -s3);
    }
}

// ================= K2: per-(b,h) complex middle, quarter-x split =================
#define K2_SMEM (8192 + 33280 + 8704 + 8704)
__global__ void __launch_bounds__(256, 3) k2_middle(const float* __restrict__ w1,
                                                    const float* __restrict__ w2,
                                                    const int* __restrict__ iq) {
    extern __shared__ char sm[];
    float2* sFq  = (float2*)sm;              // [16 xl][64 e]
    float2* sFkT = sFq + 16 * 64;            // [64 e][65 y-pad]
    float2* sA   = sFkT + 64 * 65;           // [64 y][17 xl-pad]
    float2* sC   = sA + 64 * 17;             // [64 e][17 xl-pad]

    const int bh = blockIdx.x, b = bh >> 3, h = bh & 7;
    const int x0 = blockIdx.y * 16;
    const int tid = threadIdx.x;
    const size_t QSTR = (size_t)2 * NB * NM * NCH;

    for (int i = tid; i < 1024; i += 256) {
        int xl = i >> 6, e = i & 63;
        size_t o0 = ((size_t)(b) * NM + (x0 + xl)) * NCH + h * 64 + e;
        float2 a0 = g_F[o0], a1 = g_F[o0 + QSTR], a2 = g_F[o0 + 2 * QSTR], a3 = g_F[o0 + 3 * QSTR];
        sFq[xl * 64 + e] = make_float2(a0.x + a1.x + a2.x + a3.x, a0.y + a1.y + a2.y + a3.y);
    }
    for (int i = tid; i < 4096; i += 256) {
        int e = i & 63, f = i >> 6;
        size_t o0 = ((size_t)(NB + b) * NM + f) * NCH + h * 64 + e;
        float2 a0 = g_F[o0], a1 = g_F[o0 + QSTR], a2 = g_F[o0 + 2 * QSTR], a3 = g_F[o0 + 3 * QSTR];
        sFkT[e * 65 + f] = make_float2(a0.x + a1.x + a2.x + a3.x, a0.y + a1.y + a2.y + a3.y);
    }
    __syncthreads();

    // A[x][y] = tanh_c( sum_e Fq[e,x] * Fk[e,y] )
#pragma unroll 1
    for (int p = 0; p < 4; p++) {
        int i = p * 256 + tid, xl = i >> 6, y = i & 63;
        float re = 0.f, im = 0.f;
#pragma unroll 4
        for (int e = 0; e < 64; e++) {
            float2 a = sFq[xl * 64 + e];
            float2 c = sFkT[e * 65 + y];
            re += a.x * c.x - a.y * c.y;
            im += a.x * c.y + a.y * c.x;
        }
        sA[y * 17 + xl] = make_float2(tanhf(re), tanhf(im));
    }
    __syncthreads();

    // C[e][x] = sum_y A[x,y] * Fk[e,y]
#pragma unroll 1
    for (int p = 0; p < 4; p++) {
        int i = p * 256 + tid, xl = i & 15, e = i >> 4;
        float re = 0.f, im = 0.f;
#pragma unroll 4
        for (int y = 0; y < 64; y++) {
            float2 a  = sA[y * 17 + xl];
            float2 kv = sFkT[e * 65 + y];
            re += a.x * kv.x - a.y * kv.y;
            im += a.x * kv.y + a.y * kv.x;
        }
        sC[e * 17 + xl] = make_float2(re, im);
    }
    __syncthreads();

    // O[o][x] = sum_e C[e,x] * (w1 + i w2)[h,e,o,x]; pre-scale for irfft
#pragma unroll 1
    for (int p = 0; p < 4; p++) {
        int i = p * 256 + tid, xl = i & 15, o = i >> 4, x = x0 + xl;
        float re = 0.f, im = 0.f;
        size_t wbase = (((size_t)h * 64) * 64 + o) * 64 + x;
#pragma unroll 4
        for (int e = 0; e < 64; e++) {
            float2 c = sC[e * 17 + xl];
            float wr = w1[wbase + (size_t)e * 4096];
            float wi = w2[wbase + (size_t)e * 4096];
            re += c.x * wr - c.y * wi;
            im += c.x * wi + c.y * wr;
        }
        int fx = iq[x];
        float s = ((fx == 0) || (fx == NL / 2) ? 1.0f : 2.0f) * 9.313225746154785e-10f; // 2^-30
        int row = (b * 8 + h) * 64 + o;
        g_O[(size_t)row * NM + x] = make_float2(s * re, -s * im);
    }
}

// ================= K3: inverse sparse DFT (radix-4, 64 rows/CTA, 2 rows/lane, 8 t'/warp) =================
// S0 = (P0+P2)+O, S2 = (P0+P2)-O, S1 = (P0-P2)+R, S3 = (P0-P2)-R
// O = P1+P3, R = Q1-Q3;  P = A cc + B ss, Q = B cc - A ss
#define K3_SMEM (4096 * 16 + 64 * 66 * 4 * 2 + 64 * 129 * 4 + 64 * 8 + 64)
__global__ void __launch_bounds__(512, 1) k3_inverse(float* __restrict__ out,
                                                     const int* __restrict__ iq) {
    extern __shared__ char sm[];
    ulonglong2* ts2 = (ulonglong2*)sm;            // 64KB
    float* sA = (float*)(ts2 + 4096);             // [f][66] rows (pad)
    float* sB = sA + 64 * 66;
    float* sT = sB + 64 * 66;                     // [64 rows][129]
    int2* sperm = (int2*)(sT + 64 * 129);
    int* soff = (int*)(sperm + 64);

    const int rt = blockIdx.x;                    // 64 row tiles of 64
    const int tq = blockIdx.y;                    // 4 t' quarters
    const int r0 = rt * 64;
    const int tid = threadIdx.x, lane = tid & 31, warp = tid >> 5;

    for (int i = tid; i < 4096; i += 512) ts2[i] = g_ts[i];
    for (int i = tid; i < 4096; i += 512) {
        int rr = i >> 6, f = i & 63;
        float2 v = g_O[(size_t)(r0 + rr) * NM + f];
        sA[f * 66 + rr] = v.x;
        sB[f * 66 + rr] = v.y;
    }
    if (warp == 0) {
        const unsigned FULL = 0xffffffffu;
        int Flo = iq[lane], Fhi = iq[lane + 32];
        int clo = Flo & 3, chi = Fhi & 3;
        unsigned mlo[4], mhi[4];
        int off[5]; off[0] = 0;
#pragma unroll
        for (int c = 0; c < 4; c++) {
            mlo[c] = __ballot_sync(FULL, clo == c);
            mhi[c] = __ballot_sync(FULL, chi == c);
        }
#pragma unroll
        for (int c = 0; c < 4; c++) off[c + 1] = off[c] + __popc(mlo[c]) + __popc(mhi[c]);
        unsigned lmm = (1u << lane) - 1u;
        int p_lo = off[clo] + __popc(mlo[clo] & lmm);
        int p_hi = off[chi] + __popc(mlo[chi]) + __popc(mhi[chi] & lmm);
        sperm[p_lo] = make_int2(lane, Flo);
        sperm[p_hi] = make_int2(lane + 32, Fhi);
        if (lane < 5) soff[lane] = off[lane];
    }
    __syncthreads();

    const u64x* sAd = (const u64x*)sA;   // 33 u64x per f
    const u64x* sBd = (const u64x*)sB;
    const int o0 = soff[0], o1 = soff[1], o2 = soff[2], o3 = soff[3], o4 = soff[4];

#pragma unroll 1
    for (int pass = 0; pass < 2; pass++) {
        const int t0 = tq * 256 + pass * 128 + warp * 8;
        u64x P0[8], P2[8], O[8], R[8];
#pragma unroll
        for (int j = 0; j < 8; j++) { P0[j] = 0; P2[j] = 0; O[j] = 0; R[j] = 0; }

        // class 0 -> P0
#pragma unroll 2
        for (int pos = o0; pos < o1; pos++) {
            int2 pf = sperm[pos];
            u64x A = sAd[pf.x * 33 + lane], B = sBd[pf.x * 33 + lane];
            int id = (pf.y * t0) & 4095;
#pragma unroll
            for (int j = 0; j < 8; j++) {
                ulonglong2 cs = ts2[id];
                P0[j] = fma2(A, cs.x, P0[j]);  P0[j] = fma2(B, cs.y, P0[j]);
                id = (id + pf.y) & 4095;
            }
        }
        // class 1 -> O += P, R += Q
#pragma unroll 2
        for (int pos = o1; pos < o2; pos++) {
            int2 pf = sperm[pos];
            u64x A = sAd[pf.x * 33 + lane], B = sBd[pf.x * 33 + lane];
            u64x nA = neg2(A);
            int id = (pf.y * t0) & 4095;
#pragma unroll
            for (int j = 0; j < 8; j++) {
                ulonglong2 cs = ts2[id];
                O[j] = fma2(A, cs.x, O[j]);   O[j] = fma2(B, cs.y, O[j]);
                R[j] = fma2(B, cs.x, R[j]);   R[j] = fma2(nA, cs.y, R[j]);
                id = (id + pf.y) & 4095;
            }
        }
        // class 2 -> P2
#pragma unroll 2
        for (int pos = o2; pos < o3; pos++) {
            int2 pf = sperm[pos];
            u64x A = sAd[pf.x * 33 + lane], B = sBd[pf.x * 33 + lane];
            int id = (pf.y * t0) & 4095;
#pragma unroll
            for (int j = 0; j < 8; j++) {
                ulonglong2 cs = ts2[id];
                P2[j] = fma2(A, cs.x, P2[j]);  P2[j] = fma2(B, cs.y, P2[j]);
                id = (id + pf.y) & 4095;
            }
        }
        // class 3 -> O += P, R -= Q
#pragma unroll 2
        for (int pos = o3; pos < o4; pos++) {
            int2 pf = sperm[pos];
            u64x A = sAd[pf.x * 33 + lane], B = sBd[pf.x * 33 + lane];
            u64x nB = neg2(B);
            int id = (pf.y * t0) & 4095;
#pragma unroll
            for (int j = 0; j < 8; j++) {
                ulonglong2 cs = ts2[id];
                O[j] = fma2(A, cs.x, O[j]);   O[j] = fma2(B, cs.y, O[j]);
                R[j] = fma2(nB, cs.x, R[j]);  R[j] = fma2(A, cs.y, R[j]);
                id = (id + pf.y) & 4095;
            }
        }

        // reconstruct 4 quadrants, transpose through sT, store
#pragma unroll 1
        for (int m = 0; m < 4; m++) {
            __syncthreads();
#pragma unroll
            for (int j = 0; j < 8; j++) {
                u64x Ps = add2(P0[j], P2[j]);
                u64x Pd = sub2(P0[j], P2[j]);
                u64x S;
                if (m == 0)      S = add2(Ps, O[j]);
                else if (m == 1) S = add2(Pd, R[j]);
                else if (m == 2) S = sub2(Ps, O[j]);
                else             S = sub2(Pd, R[j]);
                float v0, v1;
                unpack2(S, v0, v1);
                int tl = warp * 8 + j;
                sT[(2 * lane) * 129 + tl]       = v0;
                sT[(2 * lane + 1) * 129 + tl]   = v1;
            }
            __syncthreads();
            int tbase = m * 1024 + tq * 256 + pass * 128;
#pragma unroll
            for (int ii = 0; ii < 4; ii++) {
                int i = ii * 512 + tid;        // 2048 float4
                int rr = i >> 5, c4 = i & 31;
                const float* sp = sT + rr * 129 + c4 * 4;
                float4 vv = make_float4(sp[0], sp[1], sp[2], sp[3]);
                *(float4*)&out[(size_t)(r0 + rr) * NL + tbase + c4 * 4] = vv;
            }
        }
    }
}

// ================= launch =================
extern "C" void kernel_launch(void* const* d_in, const int* in_sizes, int n_in,
                              void* d_out, int out_size) {
    const float* q  = (const float*)d_in[0];
    const float* k  = (const float*)d_in[1];
    // d_in[2] = v, never used by the reference
    const float* w1 = (const float*)d_in[3];
    const float* w2 = (const float*)d_in[4];
    const int* iq   = (const int*)d_in[5];
    const int* ikv  = (const int*)d_in[6];
    float* out = (float*)d_out;

    cudaFuncSetAttribute(k1_forward, cudaFuncAttributeMaxDynamicSharedMemorySize, K1_SMEM);
    cudaFuncSetAttribute(k2_middle,  cudaFuncAttributeMaxDynamicSharedMemorySize, K2_SMEM);
    cudaFuncSetAttribute(k3_inverse, cudaFuncAttributeMaxDynamicSharedMemorySize, K3_SMEM);

    k0_init<<<16, 256>>>();
    k1_forward<<<dim3(4, NB, 8), 256, K1_SMEM>>>(q, k, iq, ikv);
    k2_middle<<<dim3(NB * NH, 4), 256, K2_SMEM>>>(w1, w2, iq);
    k3_inverse<<<dim3(64, 4), 512, K3_SMEM>>>(out, iq);
}

// round 8
// speedup vs baseline: 1.0280x; 1.0280x over previous
#include <cuda_runtime.h>
#include <math.h>

#define NB 8
#define NL 4096
#define NH 8
#define NM 64
#define NCH 512

typedef unsigned long long u64x;

// ---------------- device scratch ----------------
__device__ ulonglong2 g_ts[4096];                  // (cc, ss) packed f32x2 of angle 2*pi*i/4096
__device__ float2 g_F[8 * NB * NM * NCH];          // [tq*2+tensor][b][mode-pos][ch]
__device__ float2 g_O[NB * NH * 64 * NM];          // [row][mode-pos]: (A, B) pre-scaled

// ---------------- f32x2 helpers ----------------
static __device__ __forceinline__ u64x fma2(u64x a, u64x b, u64x c) {
    u64x d; asm("fma.rn.f32x2 %0,%1,%2,%3;" : "=l"(d) : "l"(a), "l"(b), "l"(c)); return d;
}
static __device__ __forceinline__ u64x add2(u64x a, u64x b) {
    u64x d; asm("add.rn.f32x2 %0,%1,%2;" : "=l"(d) : "l"(a), "l"(b)); return d;
}
#define NEG1X2 0xBF800000BF800000ULL
#define KK2    0x3F3504F33F3504F3ULL   // (sqrt2/2, sqrt2/2)
#define NKK2   0xBF3504F3BF3504F3ULL   // negated
static __device__ __forceinline__ u64x sub2(u64x a, u64x b) { return fma2(b, NEG1X2, a); }
static __device__ __forceinline__ u64x neg2(u64x a) { return fma2(a, NEG1X2, 0ULL); }
static __device__ __forceinline__ void unpack2(u64x d, float& lo, float& hi) {
    asm("mov.b64 {%0,%1},%2;" : "=f"(lo), "=f"(hi) : "l"(d));
}

// ================= K0: trig table =================
__global__ void k0_init() {
    int i = blockIdx.x * 256 + threadIdx.x;
    if (i < 4096) {
        float s, c;
        sincospif((float)i / 2048.0f, &s, &c);
        u64x cc, ss;
        asm("mov.b64 %0,{%1,%1};" : "=l"(cc) : "f"(c));
        asm("mov.b64 %0,{%1,%1};" : "=l"(ss) : "f"(s));
        g_ts[i] = make_ulonglong2(cc, ss);
    }
}

// ================= K1: forward sparse DFT (radix-8, 8 modes/warp, 4 ch/lane) =================
// X[f] = sum_{t'} u_j(t') e^{-i 2pi f t'/4096}, j=f&7, u_j = sum_m x[t'+512m] w^{jm}, w=e^{-i pi/4}.
// accR=Re, accS accumulates -Im.  Loads are contiguous LDS.128 per lane (ulonglong2).
template<int CLS>
static __device__ __forceinline__ void k1_chunk8(
    const ulonglong2* __restrict__ xs2, const ulonglong2* __restrict__ ts2,
    int lane, u64x accR[16], u64x accS[16], int idx[8], const int F[8])
{
#pragma unroll 2
    for (int tt = 0; tt < 8; tt++) {
        ulonglong2 X0 = xs2[(0 * 8 + tt) * 32 + lane];
        ulonglong2 X1 = xs2[(1 * 8 + tt) * 32 + lane];
        ulonglong2 X2 = xs2[(2 * 8 + tt) * 32 + lane];
        ulonglong2 X3 = xs2[(3 * 8 + tt) * 32 + lane];
        ulonglong2 X4 = xs2[(4 * 8 + tt) * 32 + lane];
        ulonglong2 X5 = xs2[(5 * 8 + tt) * 32 + lane];
        ulonglong2 X6 = xs2[(6 * 8 + tt) * 32 + lane];
        ulonglong2 X7 = xs2[(7 * 8 + tt) * 32 + lane];
        u64x Pr[2], Pi[2], nPi[2];
#pragma unroll
        for (int p = 0; p < 2; p++) {
            u64x a0 = p ? X0.y : X0.x;
            u64x a1 = p ? X1.y : X1.x;
            u64x a2 = p ? X2.y : X2.x;
            u64x a3 = p ? X3.y : X3.x;
            u64x a4 = p ? X4.y : X4.x;
            u64x a5 = p ? X5.y : X5.x;
            u64x a6 = p ? X6.y : X6.x;
            u64x a7 = p ? X7.y : X7.x;
            if (CLS == 0) {
                Pr[p] = add2(add2(add2(a0, a4), add2(a2, a6)), add2(add2(a1, a5), add2(a3, a7)));
            } else if (CLS == 4) {
                Pr[p] = sub2(add2(add2(a0, a4), add2(a2, a6)), add2(add2(a1, a5), add2(a3, a7)));
            } else if (CLS == 2 || CLS == 6) {
                u64x e0 = add2(a0, a4), e2 = add2(a2, a6);
                u64x e1 = add2(a1, a5), e3 = add2(a3, a7);
                Pr[p] = sub2(e0, e2);
                Pi[p] = (CLS == 2) ? sub2(e3, e1) : sub2(e1, e3);
                nPi[p] = neg2(Pi[p]);
            } else {
                u64x d04 = sub2(a0, a4), d62 = sub2(a6, a2);
                u64x s1 = sub2(a1, a5), s2 = sub2(a3, a7);
                u64x t1 = sub2(s1, s2), t2 = add2(s1, s2);
                if (CLS == 1) { Pr[p] = fma2(t1, KK2, d04);  Pi[p] = fma2(t2, NKK2, d62); }
                if (CLS == 3) { Pr[p] = fma2(t1, NKK2, d04); Pi[p] = neg2(fma2(t2, KK2, d62)); }
                if (CLS == 5) { Pr[p] = fma2(t1, NKK2, d04); Pi[p] = fma2(t2, KK2, d62); }
                if (CLS == 7) { Pr[p] = fma2(t1, KK2, d04);  Pi[p] = fma2(t2, KK2, neg2(d62)); }
                nPi[p] = neg2(Pi[p]);
            }
        }
#pragma unroll
        for (int k = 0; k < 8; k++) {
            ulonglong2 cs = ts2[idx[k]];
#pragma unroll
            for (int p = 0; p < 2; p++) {
                accR[k * 2 + p] = fma2(Pr[p], cs.x, accR[k * 2 + p]);
                accS[k * 2 + p] = fma2(Pr[p], cs.y, accS[k * 2 + p]);
                if (CLS != 0 && CLS != 4) {
                    accR[k * 2 + p] = fma2(Pi[p],  cs.y, accR[k * 2 + p]);
                    accS[k * 2 + p] = fma2(nPi[p], cs.x, accS[k * 2 + p]);
                }
            }
            idx[k] = (idx[k] + F[k]) & 4095;
        }
    }
}

// generic (mixed-class) fallback: direct per-row accumulation, no decimation
static __device__ __forceinline__ void k1_chunk_gen(
    const ulonglong2* __restrict__ xs2, const ulonglong2* __restrict__ ts2,
    int lane, u64x accR[16], u64x accS[16], int tp0, const int F[8])
{
    for (int tt = 0; tt < 8; tt++) {
#pragma unroll
        for (int m = 0; m < 8; m++) {
            ulonglong2 x = xs2[(m * 8 + tt) * 32 + lane];
            int tg = tp0 + tt + 512 * m;
#pragma unroll
            for (int k = 0; k < 8; k++) {
                int id = (F[k] * tg) & 4095;
                ulonglong2 cs = ts2[id];
                accR[k * 2 + 0] = fma2(x.x, cs.x, accR[k * 2 + 0]);
                accS[k * 2 + 0] = fma2(x.x, cs.y, accS[k * 2 + 0]);
                accR[k * 2 + 1] = fma2(x.y, cs.x, accR[k * 2 + 1]);
                accS[k * 2 + 1] = fma2(x.y, cs.y, accS[k * 2 + 1]);
            }
        }
    }
}

#define K1_SMEM (4096 * 16 + 8 * 8 * 128 * 4 + 256)
__global__ void __launch_bounds__(256, 2) k1_forward(const float* __restrict__ qp,
                                                     const float* __restrict__ kp,
                                                     const int* __restrict__ iq,
                                                     const int* __restrict__ ikv) {
    extern __shared__ char sm[];
    ulonglong2* ts2 = (ulonglong2*)sm;
    float* xs = (float*)(ts2 + 4096);            // [8 m][8 t'][128 ch]
    int* sMi = (int*)(xs + 8 * 8 * 128);         // [64]
    const ulonglong2* xs2 = (const ulonglong2*)xs;

    const int ctile = blockIdx.x, b = blockIdx.y;
    const int tensor = blockIdx.z >> 2, tq = blockIdx.z & 3;
    const float* src = tensor ? kp : qp;
    const int* idxarr = tensor ? ikv : iq;
    const int tid = threadIdx.x, lane = tid & 31, warp = tid >> 5;

    for (int i = tid; i < 4096; i += 256) ts2[i] = g_ts[i];

    // bucket 64 modes by class (F&7); warp takes bucketed block per SMSP-balancing perm
    const int wperm_tab[8] = {0, 4, 2, 6, 1, 3, 5, 7};
    const int gw = wperm_tab[warp];
    const unsigned FULL = 0xffffffffu;
    int Flo = idxarr[lane], Fhi = idxarr[lane + 32];
    int clo = Flo & 7, chi = Fhi & 7;
    unsigned mlo[8], mhi[8];
    int off[9]; off[0] = 0;
#pragma unroll
    for (int c = 0; c < 8; c++) {
        mlo[c] = __ballot_sync(FULL, clo == c);
        mhi[c] = __ballot_sync(FULL, chi == c);
    }
#pragma unroll
    for (int c = 0; c < 8; c++) off[c + 1] = off[c] + __popc(mlo[c]) + __popc(mhi[c]);
    unsigned lm = (1u << lane) - 1u;
    int p_lo = off[clo] + __popc(mlo[clo] & lm);
    int p_hi = off[chi] + __popc(mlo[chi]) + __popc(mhi[chi] & lm);
    int F[8];
#pragma unroll
    for (int k = 0; k < 8; k++) {
        int tpos = gw * 8 + k;
        unsigned ba = __ballot_sync(FULL, p_lo == tpos);
        unsigned bb = __ballot_sync(FULL, p_hi == tpos);
        int m = ba ? (__ffs(ba) - 1) : (32 + __ffs(bb) - 1);
        if (lane == 0) sMi[tpos] = m;
        F[k] = __shfl_sync(FULL, (m < 32) ? Flo : Fhi, m & 31);
    }
    int jcls = F[0] & 7;
    bool uni = true;
#pragma unroll
    for (int k = 1; k < 8; k++) uni = uni && ((F[k] & 7) == jcls);

    u64x accR[16], accS[16]; int idx[8];
#pragma unroll
    for (int k = 0; k < 16; k++) { accR[k] = 0; accS[k] = 0; }

    const float* base = src + (size_t)b * NL * NCH + ctile * 128;

    for (int cc = 0; cc < 16; cc++) {
        const int tp0 = tq * 128 + cc * 8;
        __syncthreads();
#pragma unroll
        for (int ii = 0; ii < 8; ii++) {
            int i = ii * 256 + tid;                 // 2048 float4
            int c4 = i & 31, tt = (i >> 5) & 7, m = i >> 8;
            ((float4*)xs)[i] = *(const float4*)(base + (size_t)(tp0 + tt + 512 * m) * NCH + c4 * 4);
        }
        __syncthreads();
#pragma unroll
        for (int k = 0; k < 8; k++) idx[k] = (F[k] * tp0) & 4095;
        if (uni) {
            switch (jcls) {
                case 0: k1_chunk8<0>(xs2, ts2, lane, accR, accS, idx, F); break;
                case 1: k1_chunk8<1>(xs2, ts2, lane, accR, accS, idx, F); break;
                case 2: k1_chunk8<2>(xs2, ts2, lane, accR, accS, idx, F); break;
                case 3: k1_chunk8<3>(xs2, ts2, lane, accR, accS, idx, F); break;
                case 4: k1_chunk8<4>(xs2, ts2, lane, accR, accS, idx, F); break;
                case 5: k1_chunk8<5>(xs2, ts2, lane, accR, accS, idx, F); break;
                case 6: k1_chunk8<6>(xs2, ts2, lane, accR, accS, idx, F); break;
                default: k1_chunk8<7>(xs2, ts2, lane, accR, accS, idx, F); break;
            }
        } else {
            k1_chunk_gen(xs2, ts2, lane, accR, accS, tp0, F);
        }
    }

    const int ch = ctile * 128 + lane * 4;
    float2* dst = g_F + ((size_t)((tq * 2 + tensor) * NB + b) * NM) * NCH;
#pragma unroll
    for (int k = 0; k < 8; k++) {
        float r0, r1, r2, r3, s0, s1, s2, s3;
        unpack2(accR[k * 2 + 0], r0, r1);
        unpack2(accS[k * 2 + 0], s0, s1);
        unpack2(accR[k * 2 + 1], r2, r3);
        unpack2(accS[k * 2 + 1], s2, s3);
        int mi = sMi[gw * 8 + k];
        float2* dp = &dst[(size_t)mi * NCH + ch];
        *(float4*)(dp)     = make_float4(r0, -s0, r1, -s1);
        *(float4*)(dp + 2) = make_float4(r2, -s2, r3, -s3);
    }
}

// ================= K2: per-(b,h) complex middle, quarter-x split =================
#define K2_SMEM (8192 + 33280 + 8704 + 8704)
__global__ void __launch_bounds__(256, 3) k2_middle(const float* __restrict__ w1,
                                                    const float* __restrict__ w2,
                                                    const int* __restrict__ iq) {
    extern __shared__ char sm[];
    float2* sFq  = (float2*)sm;              // [16 xl][64 e]
    float2* sFkT = sFq + 16 * 64;            // [64 e][65 y-pad]
    float2* sA   = sFkT + 64 * 65;           // [64 y][17 xl-pad]
    float2* sC   = sA + 64 * 17;             // [64 e][17 xl-pad]

    const int bh = blockIdx.x, b = bh >> 3, h = bh & 7;
    const int x0 = blockIdx.y * 16;
    const int tid = threadIdx.x;
    const size_t QSTR = (size_t)2 * NB * NM * NCH;

    for (int i = tid; i < 1024; i += 256) {
        int xl = i >> 6, e = i & 63;
        size_t o0 = ((size_t)(b) * NM + (x0 + xl)) * NCH + h * 64 + e;
        float2 a0 = g_F[o0], a1 = g_F[o0 + QSTR], a2 = g_F[o0 + 2 * QSTR], a3 = g_F[o0 + 3 * QSTR];
        sFq[xl * 64 + e] = make_float2(a0.x + a1.x + a2.x + a3.x, a0.y + a1.y + a2.y + a3.y);
    }
    for (int i = tid; i < 4096; i += 256) {
        int e = i & 63, f = i >> 6;
        size_t o0 = ((size_t)(NB + b) * NM + f) * NCH + h * 64 + e;
        float2 a0 = g_F[o0], a1 = g_F[o0 + QSTR], a2 = g_F[o0 + 2 * QSTR], a3 = g_F[o0 + 3 * QSTR];
        sFkT[e * 65 + f] = make_float2(a0.x + a1.x + a2.x + a3.x, a0.y + a1.y + a2.y + a3.y);
    }
    __syncthreads();

    // A[x][y] = tanh_c( sum_e Fq[e,x] * Fk[e,y] )
#pragma unroll 1
    for (int p = 0; p < 4; p++) {
        int i = p * 256 + tid, xl = i >> 6, y = i & 63;
        float re = 0.f, im = 0.f;
#pragma unroll 4
        for (int e = 0; e < 64; e++) {
            float2 a = sFq[xl * 64 + e];
            float2 c = sFkT[e * 65 + y];
            re += a.x * c.x - a.y * c.y;
            im += a.x * c.y + a.y * c.x;
        }
        sA[y * 17 + xl] = make_float2(tanhf(re), tanhf(im));
    }
    __syncthreads();

    // C[e][x] = sum_y A[x,y] * Fk[e,y]
#pragma unroll 1
    for (int p = 0; p < 4; p++) {
        int i = p * 256 + tid, xl = i & 15, e = i >> 4;
        float re = 0.f, im = 0.f;
#pragma unroll 4
        for (int y = 0; y < 64; y++) {
            float2 a  = sA[y * 17 + xl];
            float2 kv = sFkT[e * 65 + y];
            re += a.x * kv.x - a.y * kv.y;
            im += a.x * kv.y + a.y * kv.x;
        }
        sC[e * 17 + xl] = make_float2(re, im);
    }
    __syncthreads();

    // O[o][x] = sum_e C[e,x] * (w1 + i w2)[h,e,o,x]; pre-scale for irfft
#pragma unroll 1
    for (int p = 0; p < 4; p++) {
        int i = p * 256 + tid, xl = i & 15, o = i >> 4, x = x0 + xl;
        float re = 0.f, im = 0.f;
        size_t wbase = (((size_t)h * 64) * 64 + o) * 64 + x;
#pragma unroll 4
        for (int e = 0; e < 64; e++) {
            float2 c = sC[e * 17 + xl];
            float wr = w1[wbase + (size_t)e * 4096];
            float wi = w2[wbase + (size_t)e * 4096];
            re += c.x * wr - c.y * wi;
            im += c.x * wi + c.y * wr;
        }
        int fx = iq[x];
        float s = ((fx == 0) || (fx == NL / 2) ? 1.0f : 2.0f) * 9.313225746154785e-10f; // 2^-30
        int row = (b * 8 + h) * 64 + o;
        g_O[(size_t)row * NM + x] = make_float2(s * re, -s * im);
    }
}

// ================= K3: inverse sparse DFT (radix-4, 128 rows/CTA, 4 rows/lane) =================
// S0 = (P0+P2)+O, S2 = (P0+P2)-O, S1 = (P0-P2)+R, S3 = (P0-P2)-R
// O = P1+P3, R = Q1-Q3;  P = A cc + B ss, Q = B cc - A ss
#define K3_SMEM (4096 * 16 + 32768 + 32768 + 128 * 65 * 4 + 64 * 8 + 64)
__global__ void __launch_bounds__(512, 1) k3_inverse(float* __restrict__ out,
                                                     const int* __restrict__ iq) {
    extern __shared__ char sm[];
    ulonglong2* ts2 = (ulonglong2*)sm;            // 64KB
    float* sA = (float*)(ts2 + 4096);             // [f][128 slots]
    float* sB = sA + 64 * 128;
    float* sT = sB + 64 * 128;                    // [128 rows][65]
    int2* sperm = (int2*)(sT + 128 * 65);
    int* soff = (int*)(sperm + 64);

    const int rt = blockIdx.x;                    // 32 row tiles of 128
    const int tq = blockIdx.y;                    // 4 t' quarters
    const int r0 = rt * 128;
    const int tid = threadIdx.x, lane = tid & 31, warp = tid >> 5;

    for (int i = tid; i < 4096; i += 512) ts2[i] = g_ts[i];
    // load g_O: slot layout so one LDS.128 per f gives rows (2l,2l+1,64+2l,64+2l+1)
    for (int i = tid; i < 8192; i += 512) {
        int rr = i >> 6, f = i & 63;
        float2 v = g_O[(size_t)(r0 + rr) * NM + f];
        int half = rr >> 6, pr = (rr & 63) >> 1, sl = half * 2 + (rr & 1);
        sA[f * 128 + pr * 4 + sl] = v.x;
        sB[f * 128 + pr * 4 + sl] = v.y;
    }
    if (warp == 0) {
        const unsigned FULL = 0xffffffffu;
        int Flo = iq[lane], Fhi = iq[lane + 32];
        int clo = Flo & 3, chi = Fhi & 3;
        unsigned mlo[4], mhi[4];
        int off[5]; off[0] = 0;
#pragma unroll
        for (int c = 0; c < 4; c++) {
            mlo[c] = __ballot_sync(FULL, clo == c);
            mhi[c] = __ballot_sync(FULL, chi == c);
        }
#pragma unroll
        for (int c = 0; c < 4; c++) off[c + 1] = off[c] + __popc(mlo[c]) + __popc(mhi[c]);
        unsigned lmm = (1u << lane) - 1u;
        int p_lo = off[clo] + __popc(mlo[clo] & lmm);
        int p_hi = off[chi] + __popc(mlo[chi]) + __popc(mhi[chi] & lmm);
        sperm[p_lo] = make_int2(lane, Flo);
        sperm[p_hi] = make_int2(lane + 32, Fhi);
        if (lane < 5) soff[lane] = off[lane];
    }
    __syncthreads();

    const ulonglong2* sAd = (const ulonglong2*)sA;   // 32 ulonglong2 per f
    const ulonglong2* sBd = (const ulonglong2*)sB;
    const int o0 = soff[0], o1 = soff[1], o2 = soff[2], o3 = soff[3], o4 = soff[4];

#pragma unroll 1
    for (int pass = 0; pass < 4; pass++) {
        const int t0 = tq * 256 + pass * 64 + warp * 4;
        u64x P0[8], P2[8], O[8], R[8];   // [j*2 + pack]
#pragma unroll
        for (int j = 0; j < 8; j++) { P0[j] = 0; P2[j] = 0; O[j] = 0; R[j] = 0; }

        // class 0 -> P0
#pragma unroll 2
        for (int pos = o0; pos < o1; pos++) {
            int2 pf = sperm[pos];
            ulonglong2 A = sAd[pf.x * 32 + lane], B = sBd[pf.x * 32 + lane];
            int id = (pf.y * t0) & 4095;
#pragma unroll
            for (int j = 0; j < 4; j++) {
                ulonglong2 cs = ts2[id];
                P0[j * 2 + 0] = fma2(A.x, cs.x, P0[j * 2 + 0]);  P0[j * 2 + 0] = fma2(B.x, cs.y, P0[j * 2 + 0]);
                P0[j * 2 + 1] = fma2(A.y, cs.x, P0[j * 2 + 1]);  P0[j * 2 + 1] = fma2(B.y, cs.y, P0[j * 2 + 1]);
                id = (id + pf.y) & 4095;
            }
        }
        // class 1 -> O += P, R += Q
#pragma unroll 2
        for (int pos = o1; pos < o2; pos++) {
            int2 pf = sperm[pos];
            ulonglong2 A = sAd[pf.x * 32 + lane], B = sBd[pf.x * 32 + lane];
            u64x nAx = neg2(A.x), nAy = neg2(A.y);
            int id = (pf.y * t0) & 4095;
#pragma unroll
            for (int j = 0; j < 4; j++) {
                ulonglong2 cs = ts2[id];
                O[j * 2 + 0] = fma2(A.x, cs.x, O[j * 2 + 0]);   O[j * 2 + 0] = fma2(B.x, cs.y, O[j * 2 + 0]);
                O[j * 2 + 1] = fma2(A.y, cs.x, O[j * 2 + 1]);   O[j * 2 + 1] = fma2(B.y, cs.y, O[j * 2 + 1]);
                R[j * 2 + 0] = fma2(B.x, cs.x, R[j * 2 + 0]);   R[j * 2 + 0] = fma2(nAx, cs.y, R[j * 2 + 0]);
                R[j * 2 + 1] = fma2(B.y, cs.x, R[j * 2 + 1]);   R[j * 2 + 1] = fma2(nAy, cs.y, R[j * 2 + 1]);
                id = (id + pf.y) & 4095;
            }
        }
        // class 2 -> P2
#pragma unroll 2
        for (int pos = o2; pos < o3; pos++) {
            int2 pf = sperm[pos];
            ulonglong2 A = sAd[pf.x * 32 + lane], B = sBd[pf.x * 32 + lane];
            int id = (pf.y * t0) & 4095;
#pragma unroll
            for (int j = 0; j < 4; j++) {
                ulonglong2 cs = ts2[id];
                P2[j * 2 + 0] = fma2(A.x, cs.x, P2[j * 2 + 0]);  P2[j * 2 + 0] = fma2(B.x, cs.y, P2[j * 2 + 0]);
                P2[j * 2 + 1] = fma2(A.y, cs.x, P2[j * 2 + 1]);  P2[j * 2 + 1] = fma2(B.y, cs.y, P2[j * 2 + 1]);
                id = (id + pf.y) & 4095;
            }
        }
        // class 3 -> O += P, R -= Q
#pragma unroll 2
        for (int pos = o3; pos < o4; pos++) {
            int2 pf = sperm[pos];
            ulonglong2 A = sAd[pf.x * 32 + lane], B = sBd[pf.x * 32 + lane];
            u64x nBx = neg2(B.x), nBy = neg2(B.y);
            int id = (pf.y * t0) & 4095;
#pragma unroll
            for (int j = 0; j < 4; j++) {
                ulonglong2 cs = ts2[id];
                O[j * 2 + 0] = fma2(A.x, cs.x, O[j * 2 + 0]);   O[j * 2 + 0] = fma2(B.x, cs.y, O[j * 2 + 0]);
                O[j * 2 + 1] = fma2(A.y, cs.x, O[j * 2 + 1]);   O[j * 2 + 1] = fma2(B.y, cs.y, O[j * 2 + 1]);
                R[j * 2 + 0] = fma2(nBx, cs.x, R[j * 2 + 0]);   R[j * 2 + 0] = fma2(A.x, cs.y, R[j * 2 + 0]);
                R[j * 2 + 1] = fma2(nBy, cs.x, R[j * 2 + 1]);   R[j * 2 + 1] = fma2(A.y, cs.y, R[j * 2 + 1]);
                id = (id + pf.y) & 4095;
            }
        }

        // reconstruct 4 quadrants, transpose through sT, store
#pragma unroll 1
        for (int m = 0; m < 4; m++) {
            __syncthreads();
#pragma unroll
            for (int j = 0; j < 4; j++) {
#pragma unroll
                for (int p = 0; p < 2; p++) {
                    u64x S;
                    u64x Ps = add2(P0[j * 2 + p], P2[j * 2 + p]);
                    u64x Pd = sub2(P0[j * 2 + p], P2[j * 2 + p]);
                    if (m == 0)      S = add2(Ps, O[j * 2 + p]);
                    else if (m == 1) S = add2(Pd, R[j * 2 + p]);
                    else if (m == 2) S = sub2(Ps, O[j * 2 + p]);
                    else             S = sub2(Pd, R[j * 2 + p]);
                    float v0, v1;
                    unpack2(S, v0, v1);
                    int tl = warp * 4 + j;
                    int rbase = p * 64 + 2 * lane;
                    sT[rbase * 65 + tl]       = v0;
                    sT[(rbase + 1) * 65 + tl] = v1;
                }
            }
            __syncthreads();
            int tbase = m * 1024 + tq * 256 + pass * 64;
#pragma unroll
            for (int ii = 0; ii < 4; ii++) {
                int i = ii * 512 + tid;        // 2048 float4
                int rr = i >> 4, c4 = i & 15;
                const float* sp = sT + rr * 65 + c4 * 4;
                float4 vv = make_float4(sp[0], sp[1], sp[2], sp[3]);
                *(float4*)&out[(size_t)(r0 + rr) * NL + tbase + c4 * 4] = vv;
            }
        }
    }
}

// ================= launch =================
extern "C" void kernel_launch(void* const* d_in, const int* in_sizes, int n_in,
                              void* d_out, int out_size) {
    const float* q  = (const float*)d_in[0];
    const float* k  = (const float*)d_in[1];
    // d_in[2] = v, never used by the reference
    const float* w1 = (const float*)d_in[3];
    const float* w2 = (const float*)d_in[4];
    const int* iq   = (const int*)d_in[5];
    const int* ikv  = (const int*)d_in[6];
    float* out = (float*)d_out;

    cudaFuncSetAttribute(k1_forward, cudaFuncAttributeMaxDynamicSharedMemorySize, K1_SMEM);
    cudaFuncSetAttribute(k2_middle,  cudaFuncAttributeMaxDynamicSharedMemorySize, K2_SMEM);
    cudaFuncSetAttribute(k3_inverse, cudaFuncAttributeMaxDynamicSharedMemorySize, K3_SMEM);

    k0_init<<<16, 256>>>();
    k1_forward<<<dim3(4, NB, 8), 256, K1_SMEM>>>(q, k, iq, ikv);
    k2_middle<<<dim3(NB * NH, 4), 256, K2_SMEM>>>(w1, w2, iq);
    k3_inverse<<<dim3(32, 4), 512, K3_SMEM>>>(out, iq);
}